// round 5
// baseline (speedup 1.0000x reference)
#include <cuda_runtime.h>
#include <math.h>
#include <cfloat>

#define BB 8
#define QQ 2048
#define GG 128
#define CC 512
#define NT 512
#define NW (NT/32)           // 16 warps
#define MAXC 96
#define MAXPATH 136          // path cols: col0 + <=G matched + final

typedef unsigned long long u64;

// ---------------- device scratch (no allocation allowed) ----------------
__device__ float g_ct[BB*GG*QQ];   // transposed cost: CT[b][g][q]  (8 MB)
__device__ int   g_labels[BB*GG];
__device__ int   g_na[BB];

// ---------------- prep: normalize int inputs (int32 vs int64 on disk) ----
__global__ void prep_kernel(const int* __restrict__ lab_raw,
                            const int* __restrict__ na_raw) {
    __shared__ int nzl, nzn;
    int t = threadIdx.x;
    if (t == 0) { nzl = 0; nzn = 0; }
    __syncthreads();
    for (int k = t; k < (BB*GG)/2; k += blockDim.x)
        if (lab_raw[2*k+1] != 0) atomicExch(&nzl, 1);
    for (int k = t; k < BB/2; k += blockDim.x)
        if (na_raw[2*k+1] != 0) atomicExch(&nzn, 1);
    __syncthreads();
    bool l64 = (nzl == 0), n64 = (nzn == 0);
    for (int k = t; k < BB*GG; k += blockDim.x)
        g_labels[k] = l64 ? lab_raw[2*k] : lab_raw[k];
    if (t < BB)
        g_na[t] = n64 ? na_raw[2*t] : na_raw[t];
}

// ---------------- cost: focal-class gather + weighted sum ---------------
__global__ void cost_kernel(const float* __restrict__ sem,
                            const float* __restrict__ center,
                            const float* __restrict__ sizes,
                            const float* __restrict__ gious,
                            float* __restrict__ fc) {
    int q = blockIdx.x, b = blockIdx.y, g = threadIdx.x;
    int lab = g_labels[b*GG + g];
    float s = sem[((size_t)(b*QQ + q))*CC + lab];
    // XLA lowers lax.logistic as 0.5 + 0.5*tanh(0.5*x)
    float p = 0.5f + 0.5f * tanhf(0.5f * s);
    float pos = 0.25f * (1.0f - p) * (1.0f - p) * (-logf(p + 1e-8f));
    float neg = 0.75f * p * p * (-log1pf(-(p - 1e-8f)));
    float diff = pos - neg;
    size_t idx = ((size_t)(b*QQ + q))*GG + g;
    fc[idx] = 2.0f*diff + 5.0f*center[idx] + 1.0f*sizes[idx] - 2.0f*gious[idx];
}

// ---------------- transpose fc[b][q][g] -> CT[b][g][q] ------------------
__global__ void transpose_kernel(const float* __restrict__ fc) {
    __shared__ float tile[32][33];
    int b = blockIdx.z;
    int q0 = blockIdx.x * 32, g0 = blockIdx.y * 32;
    int x = threadIdx.x;
    for (int r = threadIdx.y; r < 32; r += 8)
        tile[r][x] = fc[((size_t)(b*QQ + q0 + r))*GG + g0 + x];
    __syncthreads();
    for (int r = threadIdx.y; r < 32; r += 8)
        g_ct[((size_t)(b*GG + g0 + r))*QQ + q0 + x] = tile[x][r];
}

// --------- order-preserving uint key for float (monotone) ---------------
__device__ __forceinline__ unsigned fkey(float f) {
    unsigned u = __float_as_uint(f);
    return (u & 0x80000000u) ? ~u : (u | 0x80000000u);
}
__device__ __forceinline__ float finv(unsigned k) {
    unsigned u = (k & 0x80000000u) ? (k & 0x7fffffffu) : ~k;
    return __uint_as_float(u);
}

// ---------------- LSA: exact replica of the reference's algorithm -------
// fp32 scan over preloaded registers -> packed (key,j) global argmin ->
// SPECULATIVE prefetch of the next row (hides L2 latency behind the fp64
// verification + barriers) -> fp64 verify of eps-candidates -> O(1) tid0
// hop; deltas replayed bit-exactly in a parallel write-back at search end.
__global__ void __launch_bounds__(NT) lsa_kernel(float* __restrict__ out_inds,
                                                 float* __restrict__ out_mask) {
    __shared__ double v[QQ + 1];        // fp64 master potentials (base during a search)
    __shared__ float  vf[QQ + 1];       // fp32 shadow (-FLT_MAX sentinel = used)
    __shared__ double u[GG + 1];
    __shared__ short  p[QQ + 1];
    __shared__ unsigned short ulist[MAXPATH];
    __shared__ double sdelta[MAXPATH];
    __shared__ u64    swp[NW];          // per-warp packed (key32 << 32 | j)
    __shared__ double cand_v[MAXC];
    __shared__ int    cand_j[MAXC];
    __shared__ int s_ncand, s_done, s_i0, s_cnt, s_bj;
    __shared__ double s_ui;
    __shared__ float  s_uif;

    int b = blockIdx.x;
    int tid = threadIdx.x;
    int lane = tid & 31, wid = tid >> 5;
    const float* CT = g_ct + (size_t)b * GG * QQ;

    int na = g_na[b];
    if (na < 0) na = 0;
    if (na > GG) na = GG;

    for (int j = tid; j <= QQ; j += NT) { v[j] = 0.0; vf[j] = 0.0f; p[j] = 0; }
    for (int j = tid; j <= GG; j += NT) u[j] = 0.0;
    __syncthreads();

    // warm prefetch: row 1 (first search scans row i=1)
    float r0 = 0.f, r1 = 0.f, r2 = 0.f, r3 = 0.f;
    int pre_i0 = -1;
    if (na > 0) {
        const float* row = CT;           // row index 1 -> CT + 0
        r0 = row[tid]; r1 = row[tid + NT]; r2 = row[tid + 2*NT]; r3 = row[tid + 3*NT];
        pre_i0 = 1;
    }

    for (int i = 1; i <= na; i++) {
        if (tid == 0) {
            p[0] = (short)i;
            ulist[0] = 0;                // column 0 joins at step 0
            s_cnt = 1;
            s_i0 = i;
            s_ui = u[i];
            s_uif = (float)u[i];
            s_ncand = 0;
            s_done = 0;
        }
        __syncthreads();                 // (A) setup / prev write-back visible

        while (true) {
            int i0 = s_i0;
            if (pre_i0 != i0) {          // mispredict / first entry: sync reload
                const float* row = CT + (size_t)(i0 - 1) * QQ;
                r0 = row[tid]; r1 = row[tid + NT];
                r2 = row[tid + 2*NT]; r3 = row[tid + 3*NT];
                pre_i0 = i0;
            }

            // ---- phase 1: fp32 scan from registers, packed warp argmin ----
            float uif = s_uif;
            int j = tid + 1;
            float c0 = (r0 - uif) - vf[j];
            float c1 = (r1 - uif) - vf[j + NT];
            float c2 = (r2 - uif) - vf[j + 2*NT];
            float c3 = (r3 - uif) - vf[j + 3*NT];
            float m = c0; int mj = j;                     // ascending j: first-index
            if (c1 < m) { m = c1; mj = j + NT; }
            if (c2 < m) { m = c2; mj = j + 2*NT; }
            if (c3 < m) { m = c3; mj = j + 3*NT; }
            u64 pk = ((u64)fkey(m) << 32) | (unsigned)mj; // lexicographic (val, j)
            #pragma unroll
            for (int off = 16; off > 0; off >>= 1) {
                u64 o = __shfl_down_sync(0xffffffffu, pk, off);
                if (o < pk) pk = o;
            }
            if (lane == 0) swp[wid] = pk;
            __syncthreads();             // (B1) warp argmins visible

            // ---- phase 2: fold global argmin, SPECULATE next row, post cands ----
            u64 g = swp[0];
            #pragma unroll
            for (int w = 1; w < NW; w++) { u64 o = swp[w]; if (o < g) g = o; }
            int gj = (int)(g & 0xffffffffu);
            float gm = finv((unsigned)(g >> 32));

            int pgj = p[gj];
            int spec = (pgj == 0) ? ((i < na) ? (i + 1) : i0) : pgj;
            const float* rown = CT + (size_t)(spec - 1) * QQ;
            float q0 = rown[tid], q1 = rown[tid + NT],
                  q2 = rown[tid + 2*NT], q3 = rown[tid + 3*NT];

            float thr = gm + 1e-3f;                  // >=20x worst-case fp32 error
            if (m <= thr) {                          // fast reject for most threads
                double uid = s_ui;
                if (c0 <= thr) {
                    double cd = ((double)r0 - uid) - v[j];
                    int slot = atomicAdd(&s_ncand, 1);
                    if (slot < MAXC) { cand_v[slot] = cd; cand_j[slot] = j; }
                }
                if (c1 <= thr) {
                    double cd = ((double)r1 - uid) - v[j + NT];
                    int slot = atomicAdd(&s_ncand, 1);
                    if (slot < MAXC) { cand_v[slot] = cd; cand_j[slot] = j + NT; }
                }
                if (c2 <= thr) {
                    double cd = ((double)r2 - uid) - v[j + 2*NT];
                    int slot = atomicAdd(&s_ncand, 1);
                    if (slot < MAXC) { cand_v[slot] = cd; cand_j[slot] = j + 2*NT; }
                }
                if (c3 <= thr) {
                    double cd = ((double)r3 - uid) - v[j + 3*NT];
                    int slot = atomicAdd(&s_ncand, 1);
                    if (slot < MAXC) { cand_v[slot] = cd; cand_j[slot] = j + 3*NT; }
                }
            }
            __syncthreads();             // (B2) candidates posted

            // ---- phase 3: tid0 exact fp64 argmin + O(1) hop setup ----
            if (tid == 0) {
                int nc = s_ncand; if (nc > MAXC) nc = MAXC;
                double best = DBL_MAX; int bj = 0x7fffffff;
                for (int s = 0; s < nc; s++) {
                    double cv = cand_v[s]; int cj = cand_j[s];
                    if (cv < best || (cv == best && cj < bj)) { best = cv; bj = cj; }
                }
                int cnt = s_cnt;
                sdelta[cnt - 1] = best;  // delta of step t = cnt-1
                if (p[bj] == 0) {
                    s_bj = bj;
                    s_done = 1;          // way==0 => single-step backtrack
                } else {
                    int ni = p[bj];
                    s_i0 = ni;
                    s_ui = u[ni];        // base value (untouched during search)
                    s_uif = (float)u[ni];
                    vf[bj] = -FLT_MAX;   // mark used
                    ulist[cnt] = (unsigned short)bj;   // joins at step cnt
                    s_cnt = cnt + 1;
                    s_ncand = 0;
                }
            }
            __syncthreads();             // (B3) hop state visible

            // commit speculation (regs already in flight / arrived)
            r0 = q0; r1 = q1; r2 = q2; r3 = q3; pre_i0 = spec;
            if (s_done) break;
        }

        // ---- parallel bit-exact write-back: entry k gets deltas k..cnt-1 ----
        {
            int cnt = s_cnt;
            if (tid < cnt) {
                int jj = ulist[tid];
                int ik = p[jj];
                double uu = u[ik];
                double vv = v[jj];
                for (int t = tid; t < cnt; t++) {
                    double d = sdelta[t];
                    uu += d;
                    vv -= d;
                }
                u[ik] = uu;
                v[jj] = vv;
                if (tid > 0) vf[jj] = (float)vv;   // restore shadow (col 0 has none)
            }
            if (tid == 0) p[s_bj] = (short)i;      // assign final unmatched column
        }
        __syncthreads();                 // order write-back before next search
    }

    // outputs: proposal j-1 matched to gt p[j]-1
    for (int j = tid + 1; j <= QQ; j += NT) {
        int pj = p[j];
        size_t o = (size_t)b * QQ + (j - 1);
        out_inds[o] = (pj > 0) ? (float)(pj - 1) : 0.0f;
        out_mask[o] = (pj > 0) ? 1.0f : 0.0f;
    }
}

// ---------------- launch ------------------------------------------------
extern "C" void kernel_launch(void* const* d_in, const int* in_sizes, int n_in,
                              void* d_out, int out_size) {
    const float* sem    = (const float*)d_in[0];
    const float* center = (const float*)d_in[1];
    const float* sizes  = (const float*)d_in[2];
    const float* gious  = (const float*)d_in[3];
    const int*   labels = (const int*)d_in[4];
    const int*   na     = (const int*)d_in[5];

    float* out      = (float*)d_out;
    float* out_inds = out;
    float* out_mask = out + (size_t)BB * QQ;
    float* fc       = out + (size_t)2 * BB * QQ;   // final_cost region

    prep_kernel<<<1, 512>>>(labels, na);
    cost_kernel<<<dim3(QQ, BB), GG>>>(sem, center, sizes, gious, fc);
    transpose_kernel<<<dim3(QQ/32, GG/32, BB), dim3(32, 8)>>>(fc);
    lsa_kernel<<<BB, NT>>>(out_inds, out_mask);
}

// round 6
// speedup vs baseline: 1.0020x; 1.0020x over previous
#include <cuda_runtime.h>
#include <math.h>
#include <cfloat>

#define BB 8
#define QQ 2048
#define GG 128
#define CC 512
#define NT 512
#define NW (NT/32)           // 16 warps
#define CAND 256             // candidate ring (monotone counter, masked index)
#define MAXPATH 140          // path cols: col0 + <=G matched + slack

typedef unsigned long long u64;

// ---------------- device scratch (no allocation allowed) ----------------
__device__ float g_ct[BB*GG*QQ];   // transposed cost: CT[b][g][q]  (8 MB)
__device__ int   g_labels[BB*GG];
__device__ int   g_na[BB];

// ---------------- prep: normalize int inputs (int32 vs int64 on disk) ----
__global__ void prep_kernel(const int* __restrict__ lab_raw,
                            const int* __restrict__ na_raw) {
    __shared__ int nzl, nzn;
    int t = threadIdx.x;
    if (t == 0) { nzl = 0; nzn = 0; }
    __syncthreads();
    for (int k = t; k < (BB*GG)/2; k += blockDim.x)
        if (lab_raw[2*k+1] != 0) atomicExch(&nzl, 1);
    for (int k = t; k < BB/2; k += blockDim.x)
        if (na_raw[2*k+1] != 0) atomicExch(&nzn, 1);
    __syncthreads();
    bool l64 = (nzl == 0), n64 = (nzn == 0);
    for (int k = t; k < BB*GG; k += blockDim.x)
        g_labels[k] = l64 ? lab_raw[2*k] : lab_raw[k];
    if (t < BB)
        g_na[t] = n64 ? na_raw[2*t] : na_raw[t];
}

// ---------------- cost: focal-class gather + weighted sum ---------------
__global__ void cost_kernel(const float* __restrict__ sem,
                            const float* __restrict__ center,
                            const float* __restrict__ sizes,
                            const float* __restrict__ gious,
                            float* __restrict__ fc) {
    int q = blockIdx.x, b = blockIdx.y, g = threadIdx.x;
    int lab = g_labels[b*GG + g];
    float s = sem[((size_t)(b*QQ + q))*CC + lab];
    // XLA lowers lax.logistic as 0.5 + 0.5*tanh(0.5*x)
    float p = 0.5f + 0.5f * tanhf(0.5f * s);
    float pos = 0.25f * (1.0f - p) * (1.0f - p) * (-logf(p + 1e-8f));
    float neg = 0.75f * p * p * (-log1pf(-(p - 1e-8f)));
    float diff = pos - neg;
    size_t idx = ((size_t)(b*QQ + q))*GG + g;
    fc[idx] = 2.0f*diff + 5.0f*center[idx] + 1.0f*sizes[idx] - 2.0f*gious[idx];
}

// ---------------- transpose fc[b][q][g] -> CT[b][g][q] ------------------
__global__ void transpose_kernel(const float* __restrict__ fc) {
    __shared__ float tile[32][33];
    int b = blockIdx.z;
    int q0 = blockIdx.x * 32, g0 = blockIdx.y * 32;
    int x = threadIdx.x;
    for (int r = threadIdx.y; r < 32; r += 8)
        tile[r][x] = fc[((size_t)(b*QQ + q0 + r))*GG + g0 + x];
    __syncthreads();
    for (int r = threadIdx.y; r < 32; r += 8)
        g_ct[((size_t)(b*GG + g0 + r))*QQ + q0 + x] = tile[x][r];
}

// --------- order-preserving uint key for float (monotone) ---------------
__device__ __forceinline__ unsigned fkey(float f) {
    unsigned u = __float_as_uint(f);
    return (u & 0x80000000u) ? ~u : (u | 0x80000000u);
}
__device__ __forceinline__ float finv(unsigned k) {
    unsigned u = (k & 0x80000000u) ? (k & 0x7fffffffu) : ~k;
    return __uint_as_float(u);
}

// ---------------- LSA: exact replica of the reference's algorithm -------
// Register-resident scan (row + v-shadow in regs), per-warp REDUX mins,
// 2 barriers/iteration, fully redundant control (no tid0 serial section on
// the critical path), speculative prefetch of the next row, fp64 candidate
// verification for bit-exact argmin, lazy-delta bit-exact write-back.
__global__ void __launch_bounds__(NT) lsa_kernel(float* __restrict__ out_inds,
                                                 float* __restrict__ out_mask) {
    __shared__ double v[QQ + 1];        // fp64 master potentials (base during a search)
    __shared__ float  vf[QQ + 1];       // fp32 shadow master (refresh source)
    __shared__ double u[GG + 1];
    __shared__ short  p[QQ + 1];
    __shared__ unsigned short ulist[MAXPATH];
    __shared__ double sdelta[MAXPATH];
    __shared__ unsigned swm[NW];        // per-warp exact fp32 min key
    __shared__ unsigned swp[NW];        // per-warp quantized (key|j) packed min
    __shared__ double cand_v[CAND];
    __shared__ int    cand_j[CAND];
    __shared__ int s_ncand;             // monotone candidate counter

    int b = blockIdx.x;
    int tid = threadIdx.x;
    int lane = tid & 31, wid = tid >> 5;
    const float* CT = g_ct + (size_t)b * GG * QQ;

    int na = g_na[b];
    if (na < 0) na = 0;
    if (na > GG) na = GG;

    for (int jj = tid; jj <= QQ; jj += NT) { v[jj] = 0.0; vf[jj] = 0.0f; p[jj] = 0; }
    for (int jj = tid; jj <= GG; jj += NT) u[jj] = 0.0;
    if (tid == 0) { s_ncand = 0; ulist[0] = 0; }   // col 0 always joins at step 0
    __syncthreads();

    const int j = tid + 1;                // my 4 columns: j, j+NT, j+2NT, j+3NT
    float w0 = 0.f, w1 = 0.f, w2 = 0.f, w3 = 0.f;  // register v-shadow (sentinel -FLT_MAX = used)
    float r0 = 0.f, r1 = 0.f, r2 = 0.f, r3 = 0.f;  // current row
    int pre_i0 = -1;
    int base = 0;                         // candidate ring base (redundant)

    if (na > 0) {                          // warm prefetch: row 1
        r0 = CT[tid]; r1 = CT[tid + NT]; r2 = CT[tid + 2*NT]; r3 = CT[tid + 3*NT];
        pre_i0 = 1;
    }

    for (int i = 1; i <= na; i++) {
        if (tid == 0) p[0] = (short)i;
        int cnt = 1;                      // path length (redundant)
        int i0 = i;
        double ui = u[i];                 // LDS broadcast (post-write-back)
        float uif = (float)ui;
        int fbj = 0;

        for (;;) {
            if (pre_i0 != i0) {           // mispredict: synchronous reload (uniform)
                const float* row = CT + (size_t)(i0 - 1) * QQ;
                r0 = row[tid]; r1 = row[tid + NT];
                r2 = row[tid + 2*NT]; r3 = row[tid + 3*NT];
                pre_i0 = i0;
            }

            // ---- phase 1: register scan + two warp REDUX ----
            float c0 = (r0 - uif) - w0;
            float c1 = (r1 - uif) - w1;
            float c2 = (r2 - uif) - w2;
            float c3 = (r3 - uif) - w3;
            float m = c0; int mj = j;                 // ascending j: first-index
            if (c1 < m) { m = c1; mj = j + NT; }
            if (c2 < m) { m = c2; mj = j + 2*NT; }
            if (c3 < m) { m = c3; mj = j + 3*NT; }
            unsigned km = fkey(m);
            unsigned kp = (km & 0xFFFFF800u) | (unsigned)(mj - 1);  // 21-bit key | 11-bit col
            unsigned wkm = __reduce_min_sync(0xffffffffu, km);
            unsigned wkp = __reduce_min_sync(0xffffffffu, kp);
            if (lane == 0) { swm[wid] = wkm; swp[wid] = wkp; }
            __syncthreads();              // B1

            // ---- phase 2: fold mins, speculative prefetch, post candidates ----
            unsigned gm_ = swm[0], gp_ = swp[0];
            #pragma unroll
            for (int w = 1; w < NW; w++) { gm_ = umin(gm_, swm[w]); gp_ = umin(gp_, swp[w]); }

            int gj = (int)(gp_ & 0x7FFu) + 1;         // approx fp32 argmin column
            int pg = p[gj];
            int spec = (pg == 0) ? ((i < na) ? (i + 1) : i0) : pg;
            const float* rs = CT + (size_t)(spec - 1) * QQ;
            float q0 = rs[tid], q1 = rs[tid + NT],
                  q2 = rs[tid + 2*NT], q3 = rs[tid + 3*NT];

            float thr = finv(gm_) + 1e-3f;            // exact global fp32 min + margin
            if (m <= thr) {
                if (c0 <= thr) {
                    double cd = ((double)r0 - ui) - v[j];
                    int s = atomicAdd(&s_ncand, 1) & (CAND - 1);
                    cand_v[s] = cd; cand_j[s] = j;
                }
                if (c1 <= thr) {
                    double cd = ((double)r1 - ui) - v[j + NT];
                    int s = atomicAdd(&s_ncand, 1) & (CAND - 1);
                    cand_v[s] = cd; cand_j[s] = j + NT;
                }
                if (c2 <= thr) {
                    double cd = ((double)r2 - ui) - v[j + 2*NT];
                    int s = atomicAdd(&s_ncand, 1) & (CAND - 1);
                    cand_v[s] = cd; cand_j[s] = j + 2*NT;
                }
                if (c3 <= thr) {
                    double cd = ((double)r3 - ui) - v[j + 3*NT];
                    int s = atomicAdd(&s_ncand, 1) & (CAND - 1);
                    cand_v[s] = cd; cand_j[s] = j + 3*NT;
                }
            }
            __syncthreads();              // B2

            // ---- phase 3: fully redundant exact fp64 argmin + state update ----
            int end = s_ncand;
            double best = DBL_MAX; int bj = 0x7fffffff;
            for (int s = base; s < end; s++) {        // identical data everywhere
                int k = s & (CAND - 1);
                double cv = cand_v[k]; int cj = cand_j[k];
                if (cv < best || (cv == best && cj < bj)) { best = cv; bj = cj; }
            }
            base = end;
            if (tid == 0) sdelta[cnt - 1] = best;     // delta of step cnt-1
            int pb = p[bj];

            if (pb == 0) {
                fbj = bj;                 // way==0 => single-step backtrack
                r0 = q0; r1 = q1; r2 = q2; r3 = q3; pre_i0 = spec;  // row for next search
                break;
            }
            if (tid == 0) ulist[cnt] = (unsigned short)bj;  // joins at step cnt
            cnt++;
            i0 = pb;
            ui = u[pb];                   // base value (untouched during search)
            uif = (float)ui;
            if      (bj == j)        w0 = -FLT_MAX;   // mark used locally
            else if (bj == j + NT)   w1 = -FLT_MAX;
            else if (bj == j + 2*NT) w2 = -FLT_MAX;
            else if (bj == j + 3*NT) w3 = -FLT_MAX;
            r0 = q0; r1 = q1; r2 = q2; r3 = q3; pre_i0 = spec;      // commit speculation
        }

        __syncthreads();                  // S1: ulist/sdelta writes visible

        // ---- parallel bit-exact write-back: entry k gets deltas k..cnt-1 ----
        if (tid < cnt) {
            int jj = ulist[tid];
            int ik = p[jj];
            double uu = u[ik];
            double vv = v[jj];
            for (int t = tid; t < cnt; t++) {          // ascending t == reference order
                double d = sdelta[t];
                uu += d;
                vv -= d;
            }
            u[ik] = uu;
            v[jj] = vv;
            if (tid > 0) vf[jj] = (float)vv;           // restore shadow master
        }
        if (tid == 0) p[fbj] = (short)i;               // assign final unmatched column
        __syncthreads();                  // S2: write-back visible

        // refresh register shadow (clears sentinels, picks up new v values)
        w0 = vf[j]; w1 = vf[j + NT]; w2 = vf[j + 2*NT]; w3 = vf[j + 3*NT];
    }

    // outputs: proposal jj-1 matched to gt p[jj]-1
    for (int jj = tid + 1; jj <= QQ; jj += NT) {
        int pj = p[jj];
        size_t o = (size_t)b * QQ + (jj - 1);
        out_inds[o] = (pj > 0) ? (float)(pj - 1) : 0.0f;
        out_mask[o] = (pj > 0) ? 1.0f : 0.0f;
    }
}

// ---------------- launch ------------------------------------------------
extern "C" void kernel_launch(void* const* d_in, const int* in_sizes, int n_in,
                              void* d_out, int out_size) {
    const float* sem    = (const float*)d_in[0];
    const float* center = (const float*)d_in[1];
    const float* sizes  = (const float*)d_in[2];
    const float* gious  = (const float*)d_in[3];
    const int*   labels = (const int*)d_in[4];
    const int*   na     = (const int*)d_in[5];

    float* out      = (float*)d_out;
    float* out_inds = out;
    float* out_mask = out + (size_t)BB * QQ;
    float* fc       = out + (size_t)2 * BB * QQ;   // final_cost region

    prep_kernel<<<1, 512>>>(labels, na);
    cost_kernel<<<dim3(QQ, BB), GG>>>(sem, center, sizes, gious, fc);
    transpose_kernel<<<dim3(QQ/32, GG/32, BB), dim3(32, 8)>>>(fc);
    lsa_kernel<<<BB, NT>>>(out_inds, out_mask);
}

// round 7
// speedup vs baseline: 1.1552x; 1.1529x over previous
#include <cuda_runtime.h>
#include <math.h>
#include <cfloat>

#define BB 8
#define QQ 2048
#define GG 128
#define CC 512
#define NT 256
#define NW (NT/32)           // 8 warps
#define CP 8                 // columns per thread
#define CAND 256             // candidate ring (monotone counter, masked index)
#define MAXPATH 140          // path cols: col0 + <=G matched + slack

// ---------------- device scratch (no allocation allowed) ----------------
__device__ float g_ct[BB*GG*QQ];   // transposed cost: CT[b][g][q]  (8 MB)
__device__ int   g_labels[BB*GG];
__device__ int   g_na[BB];

// ---------------- prep: normalize int inputs (int32 vs int64 on disk) ----
__global__ void prep_kernel(const int* __restrict__ lab_raw,
                            const int* __restrict__ na_raw) {
    __shared__ int nzl, nzn;
    int t = threadIdx.x;
    if (t == 0) { nzl = 0; nzn = 0; }
    __syncthreads();
    for (int k = t; k < (BB*GG)/2; k += blockDim.x)
        if (lab_raw[2*k+1] != 0) atomicExch(&nzl, 1);
    for (int k = t; k < BB/2; k += blockDim.x)
        if (na_raw[2*k+1] != 0) atomicExch(&nzn, 1);
    __syncthreads();
    bool l64 = (nzl == 0), n64 = (nzn == 0);
    for (int k = t; k < BB*GG; k += blockDim.x)
        g_labels[k] = l64 ? lab_raw[2*k] : lab_raw[k];
    if (t < BB)
        g_na[t] = n64 ? na_raw[2*t] : na_raw[t];
}

// ---------------- cost: focal-class gather + weighted sum ---------------
__global__ void cost_kernel(const float* __restrict__ sem,
                            const float* __restrict__ center,
                            const float* __restrict__ sizes,
                            const float* __restrict__ gious,
                            float* __restrict__ fc) {
    int q = blockIdx.x, b = blockIdx.y, g = threadIdx.x;
    int lab = g_labels[b*GG + g];
    float s = sem[((size_t)(b*QQ + q))*CC + lab];
    // XLA lowers lax.logistic as 0.5 + 0.5*tanh(0.5*x)
    float p = 0.5f + 0.5f * tanhf(0.5f * s);
    float pos = 0.25f * (1.0f - p) * (1.0f - p) * (-logf(p + 1e-8f));
    float neg = 0.75f * p * p * (-log1pf(-(p - 1e-8f)));
    float diff = pos - neg;
    size_t idx = ((size_t)(b*QQ + q))*GG + g;
    fc[idx] = 2.0f*diff + 5.0f*center[idx] + 1.0f*sizes[idx] - 2.0f*gious[idx];
}

// ---------------- transpose fc[b][q][g] -> CT[b][g][q] ------------------
__global__ void transpose_kernel(const float* __restrict__ fc) {
    __shared__ float tile[32][33];
    int b = blockIdx.z;
    int q0 = blockIdx.x * 32, g0 = blockIdx.y * 32;
    int x = threadIdx.x;
    for (int r = threadIdx.y; r < 32; r += 8)
        tile[r][x] = fc[((size_t)(b*QQ + q0 + r))*GG + g0 + x];
    __syncthreads();
    for (int r = threadIdx.y; r < 32; r += 8)
        g_ct[((size_t)(b*GG + g0 + r))*QQ + q0 + x] = tile[x][r];
}

// --------- order-preserving uint key for float (monotone) ---------------
__device__ __forceinline__ unsigned fkey(float f) {
    unsigned u = __float_as_uint(f);
    return (u & 0x80000000u) ? ~u : (u | 0x80000000u);
}
__device__ __forceinline__ float finv(unsigned k) {
    unsigned u = (k & 0x80000000u) ? (k & 0x7fffffffu) : ~k;
    return __uint_as_float(u);
}

// ---------------- LSA: exact replica of the reference's algorithm -------
// 8 warps, 8 cols/thread, rows + v-shadow register-resident, per-warp REDUX
// mins, 2 barriers/iteration, redundant control, speculative next-row
// prefetch, fp64 candidate verification, lazy-delta bit-exact write-back.
__global__ void __launch_bounds__(NT) lsa_kernel(float* __restrict__ out_inds,
                                                 float* __restrict__ out_mask) {
    __shared__ double v[QQ + 1];        // fp64 master potentials (base during a search)
    __shared__ float  vf[QQ + 1];       // fp32 shadow master (refresh source)
    __shared__ double u[GG + 1];
    __shared__ short  p[QQ + 1];
    __shared__ unsigned short ulist[MAXPATH];
    __shared__ double sdelta[MAXPATH];
    __shared__ __align__(16) unsigned swm[NW];   // per-warp exact fp32 min key
    __shared__ __align__(16) unsigned swp[NW];   // per-warp quantized (key|j) min
    __shared__ double cand_v[CAND];
    __shared__ int    cand_j[CAND];
    __shared__ int s_ncand;             // monotone candidate counter

    int b = blockIdx.x;
    int tid = threadIdx.x;
    int lane = tid & 31, wid = tid >> 5;
    const float* CT = g_ct + (size_t)b * GG * QQ;

    int na = g_na[b];
    if (na < 0) na = 0;
    if (na > GG) na = GG;

    for (int jj = tid; jj <= QQ; jj += NT) { v[jj] = 0.0; vf[jj] = 0.0f; p[jj] = 0; }
    for (int jj = tid; jj <= GG; jj += NT) u[jj] = 0.0;
    if (tid == 0) { s_ncand = 0; ulist[0] = 0; }   // col 0 always joins at step 0
    __syncthreads();

    const int j = tid + 1;                // my cols: j + k*NT, k = 0..7
    float w[CP], r[CP], q[CP];
    #pragma unroll
    for (int k = 0; k < CP; k++) { w[k] = 0.f; r[k] = 0.f; q[k] = 0.f; }
    int pre_i0 = -1;
    int base = 0;                         // candidate ring base (redundant)

    if (na > 0) {                          // warm prefetch: row 1
        #pragma unroll
        for (int k = 0; k < CP; k++) r[k] = CT[tid + k*NT];
        pre_i0 = 1;
    }

    for (int i = 1; i <= na; i++) {
        if (tid == 0) p[0] = (short)i;
        int cnt = 1;                      // path length (redundant)
        int i0 = i;
        double ui = u[i];                 // LDS broadcast (post-write-back)
        float uif = (float)ui;
        int fbj = 0;

        for (;;) {
            if (pre_i0 != i0) {           // mispredict: synchronous reload (uniform)
                const float* row = CT + (size_t)(i0 - 1) * QQ;
                #pragma unroll
                for (int k = 0; k < CP; k++) r[k] = row[tid + k*NT];
                pre_i0 = i0;
            }

            // ---- phase 1: register scan + two warp REDUX ----
            float c[CP];
            #pragma unroll
            for (int k = 0; k < CP; k++) c[k] = (r[k] - uif) - w[k];
            float m = c[0]; int mj = j;                 // ascending k: first-index
            #pragma unroll
            for (int k = 1; k < CP; k++)
                if (c[k] < m) { m = c[k]; mj = j + k*NT; }
            unsigned km = fkey(m);
            unsigned kp = (km & 0xFFFFF800u) | (unsigned)(mj - 1);  // 21b key | 11b col
            unsigned wkm = __reduce_min_sync(0xffffffffu, km);
            unsigned wkp = __reduce_min_sync(0xffffffffu, kp);
            if (lane == 0) { swm[wid] = wkm; swp[wid] = wkp; }
            __syncthreads();              // B1

            // ---- phase 2: vector fold, speculative prefetch, post candidates ----
            uint4 ma = *(const uint4*)&swm[0];
            uint4 mb = *(const uint4*)&swm[4];
            uint4 pa = *(const uint4*)&swp[0];
            uint4 pb4 = *(const uint4*)&swp[4];
            unsigned gm_ = umin(umin(umin(ma.x, ma.y), umin(ma.z, ma.w)),
                                umin(umin(mb.x, mb.y), umin(mb.z, mb.w)));
            unsigned gp_ = umin(umin(umin(pa.x, pa.y), umin(pa.z, pa.w)),
                                umin(umin(pb4.x, pb4.y), umin(pb4.z, pb4.w)));

            int gj = (int)(gp_ & 0x7FFu) + 1;         // approx fp32 argmin column
            int pg = p[gj];
            int spec = (pg == 0) ? ((i < na) ? (i + 1) : i0) : pg;
            const float* rs = CT + (size_t)(spec - 1) * QQ;
            #pragma unroll
            for (int k = 0; k < CP; k++) q[k] = rs[tid + k*NT];

            float thr = finv(gm_) + 1e-3f;            // exact global fp32 min + margin
            if (m <= thr) {
                #pragma unroll
                for (int k = 0; k < CP; k++) {
                    if (c[k] <= thr) {
                        int cj = j + k*NT;
                        double cd = ((double)r[k] - ui) - v[cj];
                        int s = atomicAdd(&s_ncand, 1) & (CAND - 1);
                        cand_v[s] = cd; cand_j[s] = cj;
                    }
                }
            }
            __syncthreads();              // B2

            // ---- phase 3: fully redundant exact fp64 argmin + state update ----
            int end = s_ncand;
            double best = DBL_MAX; int bj = 0x7fffffff;
            for (int s = base; s < end; s++) {        // identical data everywhere
                int k = s & (CAND - 1);
                double cv = cand_v[k]; int cj = cand_j[k];
                if (cv < best || (cv == best && cj < bj)) { best = cv; bj = cj; }
            }
            base = end;
            if (tid == 0) sdelta[cnt - 1] = best;     // delta of step cnt-1
            int pb = p[bj];

            if (pb == 0) {
                fbj = bj;                 // way==0 => single-step backtrack
                #pragma unroll
                for (int k = 0; k < CP; k++) r[k] = q[k];
                pre_i0 = spec;            // row for next search (spec == i+1 usually)
                break;
            }
            if (tid == 0) ulist[cnt] = (unsigned short)bj;  // joins at step cnt
            cnt++;
            i0 = pb;
            ui = u[pb];                   // base value (untouched during search)
            uif = (float)ui;
            int d = bj - j;               // mark used locally if mine
            if (d >= 0 && d < CP*NT && (d & (NT-1)) == 0) w[d >> 8] = -FLT_MAX;  // NT=256
            #pragma unroll
            for (int k = 0; k < CP; k++) r[k] = q[k];
            pre_i0 = spec;                // commit speculation
        }

        __syncthreads();                  // S1: ulist/sdelta writes visible

        // ---- parallel bit-exact write-back: entry k gets deltas k..cnt-1 ----
        if (tid < cnt) {
            int jj = ulist[tid];
            int ik = p[jj];
            double uu = u[ik];
            double vv = v[jj];
            for (int t = tid; t < cnt; t++) {          // ascending t == reference order
                double d = sdelta[t];
                uu += d;
                vv -= d;
            }
            u[ik] = uu;
            v[jj] = vv;
            if (tid > 0) vf[jj] = (float)vv;           // restore shadow master
        }
        if (tid == 0) p[fbj] = (short)i;               // assign final unmatched column
        __syncthreads();                  // S2: write-back visible

        // refresh register shadow (clears sentinels, picks up new v values)
        #pragma unroll
        for (int k = 0; k < CP; k++) w[k] = vf[j + k*NT];
    }

    // outputs: proposal jj-1 matched to gt p[jj]-1
    for (int jj = tid + 1; jj <= QQ; jj += NT) {
        int pj = p[jj];
        size_t o = (size_t)b * QQ + (jj - 1);
        out_inds[o] = (pj > 0) ? (float)(pj - 1) : 0.0f;
        out_mask[o] = (pj > 0) ? 1.0f : 0.0f;
    }
}

// ---------------- launch ------------------------------------------------
extern "C" void kernel_launch(void* const* d_in, const int* in_sizes, int n_in,
                              void* d_out, int out_size) {
    const float* sem    = (const float*)d_in[0];
    const float* center = (const float*)d_in[1];
    const float* sizes  = (const float*)d_in[2];
    const float* gious  = (const float*)d_in[3];
    const int*   labels = (const int*)d_in[4];
    const int*   na     = (const int*)d_in[5];

    float* out      = (float*)d_out;
    float* out_inds = out;
    float* out_mask = out + (size_t)BB * QQ;
    float* fc       = out + (size_t)2 * BB * QQ;   // final_cost region

    prep_kernel<<<1, 512>>>(labels, na);
    cost_kernel<<<dim3(QQ, BB), GG>>>(sem, center, sizes, gious, fc);
    transpose_kernel<<<dim3(QQ/32, GG/32, BB), dim3(32, 8)>>>(fc);
    lsa_kernel<<<BB, NT>>>(out_inds, out_mask);
}

// round 8
// speedup vs baseline: 1.3019x; 1.1270x over previous
#include <cuda_runtime.h>
#include <math.h>
#include <cfloat>

#define BB 8
#define QQ 2048
#define GG 128
#define CC 512
#define NT 128
#define NW (NT/32)           // 4 warps
#define NCH 4                // column chunks (512 cols each)
#define CHW 512              // chunk width
#define CP 16                // columns per thread (4 chunks x 4 contiguous)
#define CAND 256             // candidate ring (monotone counter, masked index)
#define MAXPATH 140          // path entries: dummy + <=G matched + slack

// ---------------- device scratch (no allocation allowed) ----------------
__device__ float g_ct[BB*GG*QQ];   // transposed cost: CT[b][g][q]  (8 MB)
__device__ int   g_labels[BB*GG];
__device__ int   g_na[BB];

// ---------------- prep: normalize int inputs (int32 vs int64 on disk) ----
__global__ void prep_kernel(const int* __restrict__ lab_raw,
                            const int* __restrict__ na_raw) {
    __shared__ int nzl, nzn;
    int t = threadIdx.x;
    if (t == 0) { nzl = 0; nzn = 0; }
    __syncthreads();
    for (int k = t; k < (BB*GG)/2; k += blockDim.x)
        if (lab_raw[2*k+1] != 0) atomicExch(&nzl, 1);
    for (int k = t; k < BB/2; k += blockDim.x)
        if (na_raw[2*k+1] != 0) atomicExch(&nzn, 1);
    __syncthreads();
    bool l64 = (nzl == 0), n64 = (nzn == 0);
    for (int k = t; k < BB*GG; k += blockDim.x)
        g_labels[k] = l64 ? lab_raw[2*k] : lab_raw[k];
    if (t < BB)
        g_na[t] = n64 ? na_raw[2*t] : na_raw[t];
}

// ---------------- cost: focal-class gather + weighted sum ---------------
__global__ void cost_kernel(const float* __restrict__ sem,
                            const float* __restrict__ center,
                            const float* __restrict__ sizes,
                            const float* __restrict__ gious,
                            float* __restrict__ fc) {
    int q = blockIdx.x, b = blockIdx.y, g = threadIdx.x;
    int lab = g_labels[b*GG + g];
    float s = sem[((size_t)(b*QQ + q))*CC + lab];
    // XLA lowers lax.logistic as 0.5 + 0.5*tanh(0.5*x)
    float p = 0.5f + 0.5f * tanhf(0.5f * s);
    float pos = 0.25f * (1.0f - p) * (1.0f - p) * (-logf(p + 1e-8f));
    float neg = 0.75f * p * p * (-log1pf(-(p - 1e-8f)));
    float diff = pos - neg;
    size_t idx = ((size_t)(b*QQ + q))*GG + g;
    fc[idx] = 2.0f*diff + 5.0f*center[idx] + 1.0f*sizes[idx] - 2.0f*gious[idx];
}

// ---------------- transpose fc[b][q][g] -> CT[b][g][q] ------------------
__global__ void transpose_kernel(const float* __restrict__ fc) {
    __shared__ float tile[32][33];
    int b = blockIdx.z;
    int q0 = blockIdx.x * 32, g0 = blockIdx.y * 32;
    int x = threadIdx.x;
    for (int r = threadIdx.y; r < 32; r += 8)
        tile[r][x] = fc[((size_t)(b*QQ + q0 + r))*GG + g0 + x];
    __syncthreads();
    for (int r = threadIdx.y; r < 32; r += 8)
        g_ct[((size_t)(b*GG + g0 + r))*QQ + q0 + x] = tile[x][r];
}

// --------- order-preserving uint key for float (monotone) ---------------
__device__ __forceinline__ unsigned fkey(float f) {
    unsigned u = __float_as_uint(f);
    return (u & 0x80000000u) ? ~u : (u | 0x80000000u);
}
__device__ __forceinline__ float finv(unsigned k) {
    unsigned u = (k & 0x80000000u) ? (k & 0x7fffffffu) : ~k;
    return __uint_as_float(u);
}

// ---------------- LSA: exact replica of the reference's algorithm -------
// 4 warps, 16 cols/thread owned as 4 contiguous float4 chunks (vector LDG/
// LDS), rows + v-shadow register-resident, per-warp REDUX mins, 2 barriers
// per iteration, redundant control, speculative next-row prefetch, fp64
// candidate verification, lazy-delta bit-exact write-back.
// Columns are 0-based internally; the reference's dummy column 0 appears
// only as write-back entry 0 (updates u[i]; v[dummy] is never read).
__global__ void __launch_bounds__(NT, 1) lsa_kernel(float* __restrict__ out_inds,
                                                    float* __restrict__ out_mask) {
    __shared__ double v[QQ];            // fp64 master potentials (0-based cols)
    __shared__ __align__(16) float vf[QQ];  // fp32 shadow master (refresh source)
    __shared__ double u[GG + 1];        // rows 1..GG
    __shared__ short  p[QQ];            // matched row per col (0 = free)
    __shared__ unsigned short ulist[MAXPATH];
    __shared__ double sdelta[MAXPATH];
    __shared__ __align__(16) unsigned swm[NW];   // per-warp exact fp32 min key
    __shared__ __align__(16) unsigned swp[NW];   // per-warp quantized (key|col) min
    __shared__ double cand_v[CAND];
    __shared__ int    cand_j[CAND];
    __shared__ int s_ncand;             // monotone candidate counter

    int b = blockIdx.x;
    int tid = threadIdx.x;
    int lane = tid & 31, wid = tid >> 5;
    const float* CT = g_ct + (size_t)b * GG * QQ;
    const int cbase = tid << 2;         // my 4 cols within a chunk start here

    int na = g_na[b];
    if (na < 0) na = 0;
    if (na > GG) na = GG;

    for (int jj = tid; jj < QQ; jj += NT) { v[jj] = 0.0; vf[jj] = 0.0f; p[jj] = 0; }
    for (int jj = tid; jj <= GG; jj += NT) u[jj] = 0.0;
    if (tid == 0) { s_ncand = 0; ulist[0] = 0; }   // entry 0 = dummy column
    __syncthreads();

    float r[CP], w[CP], q[CP], c[CP];
    #pragma unroll
    for (int k = 0; k < CP; k++) { r[k] = 0.f; w[k] = 0.f; q[k] = 0.f; }
    int pre_i0 = -1;
    int base = 0;                       // candidate ring base (redundant)

    if (na > 0) {                        // warm prefetch: row 1
        #pragma unroll
        for (int ch = 0; ch < NCH; ch++) {
            float4 t = *(const float4*)(CT + ch*CHW + cbase);
            r[ch*4+0] = t.x; r[ch*4+1] = t.y; r[ch*4+2] = t.z; r[ch*4+3] = t.w;
        }
        pre_i0 = 1;
    }

    for (int i = 1; i <= na; i++) {
        int cnt = 1;                    // path length incl. dummy (redundant)
        int i0 = i;
        double ui = u[i];               // base value (u untouched during search)
        float uif = (float)ui;
        int fbj = 0;

        for (;;) {
            if (pre_i0 != i0) {         // mispredict: synchronous reload (uniform)
                const float* row = CT + (size_t)(i0 - 1) * QQ;
                #pragma unroll
                for (int ch = 0; ch < NCH; ch++) {
                    float4 t = *(const float4*)(row + ch*CHW + cbase);
                    r[ch*4+0] = t.x; r[ch*4+1] = t.y; r[ch*4+2] = t.z; r[ch*4+3] = t.w;
                }
                pre_i0 = i0;
            }

            // ---- phase 1: register scan + two warp REDUX ----
            #pragma unroll
            for (int k = 0; k < CP; k++) c[k] = (r[k] - uif) - w[k];
            float m = c[0]; int mj = cbase;            // ascending k == ascending col
            #pragma unroll
            for (int k = 1; k < CP; k++) {
                int col = (k >> 2)*CHW + cbase + (k & 3);
                if (c[k] < m) { m = c[k]; mj = col; }
            }
            unsigned km = fkey(m);
            unsigned kp = (km & 0xFFFFF800u) | (unsigned)mj;  // 21b key | 11b col
            unsigned wkm = __reduce_min_sync(0xffffffffu, km);
            unsigned wkp = __reduce_min_sync(0xffffffffu, kp);
            if (lane == 0) { swm[wid] = wkm; swp[wid] = wkp; }
            __syncthreads();            // B1

            // ---- phase 2: vector fold, speculative prefetch, post candidates ----
            uint4 ma = *(const uint4*)&swm[0];
            uint4 pa = *(const uint4*)&swp[0];
            unsigned gm_ = umin(umin(ma.x, ma.y), umin(ma.z, ma.w));
            unsigned gp_ = umin(umin(pa.x, pa.y), umin(pa.z, pa.w));

            int gj = (int)(gp_ & 0x7FFu);             // approx fp32 argmin col
            int pg = p[gj];
            int spec = (pg == 0) ? ((i < na) ? (i + 1) : i0) : pg;
            const float* rs = CT + (size_t)(spec - 1) * QQ;
            #pragma unroll
            for (int ch = 0; ch < NCH; ch++) {
                float4 t = *(const float4*)(rs + ch*CHW + cbase);
                q[ch*4+0] = t.x; q[ch*4+1] = t.y; q[ch*4+2] = t.z; q[ch*4+3] = t.w;
            }

            float thr = finv(gm_) + 1e-3f;            // exact fp32 min + margin
            if (m <= thr) {
                #pragma unroll
                for (int k = 0; k < CP; k++) {
                    if (c[k] <= thr) {
                        int col = (k >> 2)*CHW + cbase + (k & 3);
                        double cd = ((double)r[k] - ui) - v[col];
                        int s = atomicAdd(&s_ncand, 1) & (CAND - 1);
                        cand_v[s] = cd; cand_j[s] = col;
                    }
                }
            }
            __syncthreads();            // B2

            // ---- phase 3: fully redundant exact fp64 argmin + state update ----
            int end = s_ncand;
            double best = DBL_MAX; int bj = 0x7fffffff;
            for (int s = base; s < end; s++) {        // identical data everywhere
                int k = s & (CAND - 1);
                double cv = cand_v[k]; int cj = cand_j[k];
                if (cv < best || (cv == best && cj < bj)) { best = cv; bj = cj; }
            }
            base = end;
            if (tid == 0) sdelta[cnt - 1] = best;     // delta of step cnt-1
            int pb = p[bj];

            if (pb == 0) {
                fbj = bj;               // way==0 => single-step backtrack
                #pragma unroll
                for (int k = 0; k < CP; k++) r[k] = q[k];
                pre_i0 = spec;
                break;
            }
            if (tid == 0) ulist[cnt] = (unsigned short)bj;  // joins at step cnt
            cnt++;
            i0 = pb;
            ui = u[pb];                 // base value
            uif = (float)ui;
            {                            // mark used locally if one of my cols
                int o = bj - cbase;      // o == ch*CHW + (0..3) iff mine
                #pragma unroll
                for (int k = 0; k < CP; k++)
                    if (o == (k >> 2)*CHW + (k & 3)) w[k] = -FLT_MAX;
            }
            #pragma unroll
            for (int k = 0; k < CP; k++) r[k] = q[k];
            pre_i0 = spec;              // commit speculation
        }

        __syncthreads();                // S1: ulist/sdelta writes visible

        // ---- parallel bit-exact write-back: entry k gets deltas k..cnt-1 ----
        if (tid < cnt) {
            if (tid == 0) {              // dummy column: u[i] only (v[0] never read)
                double uu = u[i];
                for (int t = 0; t < cnt; t++) uu += sdelta[t];
                u[i] = uu;
            } else {
                int col = ulist[tid];
                int ik = p[col];
                double uu = u[ik];
                double vv = v[col];
                for (int t = tid; t < cnt; t++) {     // ascending t == reference order
                    double d = sdelta[t];
                    uu += d;
                    vv -= d;
                }
                u[ik] = uu;
                v[col] = vv;
                vf[col] = (float)vv;     // restore shadow master
            }
        }
        if (tid == 0) p[fbj] = (short)i;              // assign final unmatched column
        __syncthreads();                // S2: write-back visible

        // refresh register shadow (clears sentinels, picks up new v values)
        #pragma unroll
        for (int ch = 0; ch < NCH; ch++) {
            float4 t = *(const float4*)(vf + ch*CHW + cbase);
            w[ch*4+0] = t.x; w[ch*4+1] = t.y; w[ch*4+2] = t.z; w[ch*4+3] = t.w;
        }
    }

    // outputs: proposal col matched to gt p[col]-1
    for (int jj = tid; jj < QQ; jj += NT) {
        int pj = p[jj];
        size_t o = (size_t)b * QQ + jj;
        out_inds[o] = (pj > 0) ? (float)(pj - 1) : 0.0f;
        out_mask[o] = (pj > 0) ? 1.0f : 0.0f;
    }
}

// ---------------- launch ------------------------------------------------
extern "C" void kernel_launch(void* const* d_in, const int* in_sizes, int n_in,
                              void* d_out, int out_size) {
    const float* sem    = (const float*)d_in[0];
    const float* center = (const float*)d_in[1];
    const float* sizes  = (const float*)d_in[2];
    const float* gious  = (const float*)d_in[3];
    const int*   labels = (const int*)d_in[4];
    const int*   na     = (const int*)d_in[5];

    float* out      = (float*)d_out;
    float* out_inds = out;
    float* out_mask = out + (size_t)BB * QQ;
    float* fc       = out + (size_t)2 * BB * QQ;   // final_cost region

    prep_kernel<<<1, 512>>>(labels, na);
    cost_kernel<<<dim3(QQ, BB), GG>>>(sem, center, sizes, gious, fc);
    transpose_kernel<<<dim3(QQ/32, GG/32, BB), dim3(32, 8)>>>(fc);
    lsa_kernel<<<BB, NT>>>(out_inds, out_mask);
}

// round 9
// speedup vs baseline: 1.3218x; 1.0153x over previous
#include <cuda_runtime.h>
#include <math.h>
#include <cfloat>

#define BB 8
#define QQ 2048
#define GG 128
#define CC 512
#define NT 128
#define NW (NT/32)           // 4 warps
#define NCH 4                // column chunks (512 cols each)
#define CHW 512              // chunk width
#define CP 16                // columns per thread (4 chunks x 4 contiguous)
#define CAND 256             // candidate ring (monotone counter, masked index)
#define MAXPATH 140          // path entries: dummy + <=G matched + slack

// ---------------- device scratch (no allocation allowed) ----------------
__device__ float g_ct[BB*GG*QQ];   // transposed cost: CT[b][g][q]  (8 MB)
__device__ int   g_labels[BB*GG];
__device__ int   g_na[BB];

// ---------------- prep: normalize int inputs (int32 vs int64 on disk) ----
__global__ void prep_kernel(const int* __restrict__ lab_raw,
                            const int* __restrict__ na_raw) {
    __shared__ int nzl, nzn;
    int t = threadIdx.x;
    if (t == 0) { nzl = 0; nzn = 0; }
    __syncthreads();
    for (int k = t; k < (BB*GG)/2; k += blockDim.x)
        if (lab_raw[2*k+1] != 0) atomicExch(&nzl, 1);
    for (int k = t; k < BB/2; k += blockDim.x)
        if (na_raw[2*k+1] != 0) atomicExch(&nzn, 1);
    __syncthreads();
    bool l64 = (nzl == 0), n64 = (nzn == 0);
    for (int k = t; k < BB*GG; k += blockDim.x)
        g_labels[k] = l64 ? lab_raw[2*k] : lab_raw[k];
    if (t < BB)
        g_na[t] = n64 ? na_raw[2*t] : na_raw[t];
}

// ------- fused cost + transpose: fc[b][q][g] and CT[b][g][q] in one pass -----
__global__ void cost_transpose_kernel(const float* __restrict__ sem,
                                      const float* __restrict__ center,
                                      const float* __restrict__ sizes,
                                      const float* __restrict__ gious,
                                      float* __restrict__ fc) {
    __shared__ float tile[32][33];
    int b = blockIdx.z;
    int q0 = blockIdx.x * 32, g0 = blockIdx.y * 32;
    int x = threadIdx.x;
    int g = g0 + x;
    int lab = g_labels[b*GG + g];
    for (int r = threadIdx.y; r < 32; r += 8) {
        int q = q0 + r;
        float s = sem[((size_t)(b*QQ + q))*CC + lab];
        // XLA lowers lax.logistic as 0.5 + 0.5*tanh(0.5*x)
        float p = 0.5f + 0.5f * tanhf(0.5f * s);
        float pos = 0.25f * (1.0f - p) * (1.0f - p) * (-logf(p + 1e-8f));
        float neg = 0.75f * p * p * (-log1pf(-(p - 1e-8f)));
        float diff = pos - neg;
        size_t idx = ((size_t)(b*QQ + q))*GG + g;
        float val = 2.0f*diff + 5.0f*center[idx] + 1.0f*sizes[idx] - 2.0f*gious[idx];
        fc[idx] = val;                 // coalesced along g
        tile[r][x] = val;
    }
    __syncthreads();
    for (int r = threadIdx.y; r < 32; r += 8)
        g_ct[((size_t)(b*GG + g0 + r))*QQ + q0 + x] = tile[x][r];  // coalesced along q
}

// --------- order-preserving uint key for float (monotone) ---------------
__device__ __forceinline__ unsigned fkey(float f) {
    unsigned u = __float_as_uint(f);
    return (u & 0x80000000u) ? ~u : (u | 0x80000000u);
}
__device__ __forceinline__ float finv(unsigned k) {
    unsigned u = (k & 0x80000000u) ? (k & 0x7fffffffu) : ~k;
    return __uint_as_float(u);
}

// ---------------- LSA: exact replica of the reference's algorithm -------
// 4 warps, 16 cols/thread (4 contiguous float4 chunks), rows + v-shadow
// register-resident, BALANCED min/argmin trees (no serial select chain),
// per-warp REDUX mins, 2 barriers/iteration, redundant control, speculative
// next-row prefetch, fp64 candidate verification, lazy-delta write-back.
__global__ void __launch_bounds__(NT, 1) lsa_kernel(float* __restrict__ out_inds,
                                                    float* __restrict__ out_mask) {
    __shared__ double v[QQ];            // fp64 master potentials (0-based cols)
    __shared__ __align__(16) float vf[QQ];  // fp32 shadow master
    __shared__ double u[GG + 1];        // rows 1..GG
    __shared__ short  p[QQ];            // matched row per col (0 = free)
    __shared__ unsigned short ulist[MAXPATH];
    __shared__ double sdelta[MAXPATH];
    __shared__ __align__(16) unsigned swm[NW];   // per-warp exact fp32 min key
    __shared__ __align__(16) unsigned swp[NW];   // per-warp (key21|col11) min
    __shared__ double cand_v[CAND];
    __shared__ int    cand_j[CAND];
    __shared__ int s_ncand;             // monotone candidate counter

    int b = blockIdx.x;
    int tid = threadIdx.x;
    int lane = tid & 31, wid = tid >> 5;
    const float* CT = g_ct + (size_t)b * GG * QQ;
    const int cbase = tid << 2;         // my 4 cols within each chunk start here

    int na = g_na[b];
    if (na < 0) na = 0;
    if (na > GG) na = GG;

    for (int jj = tid; jj < QQ; jj += NT) { v[jj] = 0.0; vf[jj] = 0.0f; p[jj] = 0; }
    for (int jj = tid; jj <= GG; jj += NT) u[jj] = 0.0;
    if (tid == 0) { s_ncand = 0; ulist[0] = 0; }   // entry 0 = dummy column
    __syncthreads();

    float r[CP], w[CP], q[CP], c[CP];
    #pragma unroll
    for (int k = 0; k < CP; k++) { r[k] = 0.f; w[k] = 0.f; q[k] = 0.f; }
    int pre_i0 = -1;
    int base = 0;                       // candidate ring base (redundant)

    if (na > 0) {                        // warm prefetch: row 1
        #pragma unroll
        for (int ch = 0; ch < NCH; ch++) {
            float4 t = *(const float4*)(CT + ch*CHW + cbase);
            r[ch*4+0] = t.x; r[ch*4+1] = t.y; r[ch*4+2] = t.z; r[ch*4+3] = t.w;
        }
        pre_i0 = 1;
    }

    for (int i = 1; i <= na; i++) {
        int cnt = 1;                    // path length incl. dummy (redundant)
        int i0 = i;
        double ui = u[i];
        float uif = (float)ui;
        int fbj = 0;

        for (;;) {
            if (pre_i0 != i0) {         // mispredict: synchronous reload (uniform)
                const float* row = CT + (size_t)(i0 - 1) * QQ;
                #pragma unroll
                for (int ch = 0; ch < NCH; ch++) {
                    float4 t = *(const float4*)(row + ch*CHW + cbase);
                    r[ch*4+0] = t.x; r[ch*4+1] = t.y; r[ch*4+2] = t.z; r[ch*4+3] = t.w;
                }
                pre_i0 = i0;
            }

            // ---- phase 1: register scan + BALANCED min / argmin trees ----
            #pragma unroll
            for (int k = 0; k < CP; k++) c[k] = (r[k] - uif) - w[k];
            float t8[8];
            #pragma unroll
            for (int k = 0; k < 8; k++) t8[k] = fminf(c[2*k], c[2*k+1]);
            float t4a = fminf(t8[0], t8[1]), t4b = fminf(t8[2], t8[3]);
            float t4c = fminf(t8[4], t8[5]), t4d = fminf(t8[6], t8[7]);
            float m = fminf(fminf(t4a, t4b), fminf(t4c, t4d));
            // local argmin col: lowest col among exact-equal values (first-index)
            int e[CP];
            #pragma unroll
            for (int k = 0; k < CP; k++) {
                int col = (k >> 2)*CHW + cbase + (k & 3);
                e[k] = (c[k] == m) ? col : 0x7FF;
            }
            int s8[8];
            #pragma unroll
            for (int k = 0; k < 8; k++) s8[k] = min(e[2*k], e[2*k+1]);
            int s4a = min(s8[0], s8[1]), s4b = min(s8[2], s8[3]);
            int s4c = min(s8[4], s8[5]), s4d = min(s8[6], s8[7]);
            int mj = min(min(s4a, s4b), min(s4c, s4d));

            unsigned km = fkey(m);
            unsigned kp = (km & 0xFFFFF800u) | (unsigned)mj;  // 21b key | 11b col
            unsigned wkm = __reduce_min_sync(0xffffffffu, km);
            unsigned wkp = __reduce_min_sync(0xffffffffu, kp);
            if (lane == 0) { swm[wid] = wkm; swp[wid] = wkp; }
            __syncthreads();            // B1

            // ---- phase 2: vector fold, speculative prefetch, post candidates ----
            uint4 ma = *(const uint4*)&swm[0];
            uint4 pa = *(const uint4*)&swp[0];
            unsigned gm_ = umin(umin(ma.x, ma.y), umin(ma.z, ma.w));
            unsigned gp_ = umin(umin(pa.x, pa.y), umin(pa.z, pa.w));

            int gj = (int)(gp_ & 0x7FFu);             // approx fp32 argmin col
            int pg = p[gj];
            int spec = (pg == 0) ? ((i < na) ? (i + 1) : i0) : pg;
            const float* rs = CT + (size_t)(spec - 1) * QQ;
            #pragma unroll
            for (int ch = 0; ch < NCH; ch++) {
                float4 t = *(const float4*)(rs + ch*CHW + cbase);
                q[ch*4+0] = t.x; q[ch*4+1] = t.y; q[ch*4+2] = t.z; q[ch*4+3] = t.w;
            }

            float thr = finv(gm_) + 1e-3f;            // exact fp32 min + margin
            if (m <= thr) {
                #pragma unroll
                for (int k = 0; k < CP; k++) {
                    if (c[k] <= thr) {
                        int col = (k >> 2)*CHW + cbase + (k & 3);
                        double cd = ((double)r[k] - ui) - v[col];
                        int s = atomicAdd(&s_ncand, 1) & (CAND - 1);
                        cand_v[s] = cd; cand_j[s] = col;
                    }
                }
            }
            __syncthreads();            // B2

            // ---- phase 3: fully redundant exact fp64 argmin + state update ----
            int end = s_ncand;
            double best = DBL_MAX; int bj = 0x7fffffff;
            for (int s = base; s < end; s++) {        // identical data everywhere
                int k = s & (CAND - 1);
                double cv = cand_v[k]; int cj = cand_j[k];
                if (cv < best || (cv == best && cj < bj)) { best = cv; bj = cj; }
            }
            base = end;
            if (tid == 0) sdelta[cnt - 1] = best;     // delta of step cnt-1
            int pb = p[bj];

            if (pb == 0) {
                fbj = bj;               // way==0 => single-step backtrack
                #pragma unroll
                for (int k = 0; k < CP; k++) r[k] = q[k];
                pre_i0 = spec;
                break;
            }
            if (tid == 0) ulist[cnt] = (unsigned short)bj;  // joins at step cnt
            cnt++;
            i0 = pb;
            ui = u[pb];
            uif = (float)ui;
            {                            // mark used locally if one of my cols
                int o = bj - cbase;
                #pragma unroll
                for (int k = 0; k < CP; k++)
                    if (o == (k >> 2)*CHW + (k & 3)) w[k] = -FLT_MAX;
            }
            #pragma unroll
            for (int k = 0; k < CP; k++) r[k] = q[k];
            pre_i0 = spec;              // commit speculation
        }

        __syncthreads();                // S1: ulist/sdelta writes visible

        // ---- parallel bit-exact write-back: entry k gets deltas k..cnt-1 ----
        if (tid < cnt) {
            if (tid == 0) {              // dummy column: u[i] only (v[0] never read)
                double uu = u[i];
                for (int t = 0; t < cnt; t++) uu += sdelta[t];
                u[i] = uu;
            } else {
                int col = ulist[tid];
                int ik = p[col];
                double uu = u[ik];
                double vv = v[col];
                for (int t = tid; t < cnt; t++) {     // ascending t == reference order
                    double d = sdelta[t];
                    uu += d;
                    vv -= d;
                }
                u[ik] = uu;
                v[col] = vv;
                vf[col] = (float)vv;     // restore shadow master
            }
        }
        if (tid == 0) p[fbj] = (short)i;              // assign final unmatched column
        __syncthreads();                // S2: write-back visible

        // refresh register shadow (clears sentinels, picks up new v values)
        #pragma unroll
        for (int ch = 0; ch < NCH; ch++) {
            float4 t = *(const float4*)(vf + ch*CHW + cbase);
            w[ch*4+0] = t.x; w[ch*4+1] = t.y; w[ch*4+2] = t.z; w[ch*4+3] = t.w;
        }
    }

    // outputs: proposal col matched to gt p[col]-1
    for (int jj = tid; jj < QQ; jj += NT) {
        int pj = p[jj];
        size_t o = (size_t)b * QQ + jj;
        out_inds[o] = (pj > 0) ? (float)(pj - 1) : 0.0f;
        out_mask[o] = (pj > 0) ? 1.0f : 0.0f;
    }
}

// ---------------- launch ------------------------------------------------
extern "C" void kernel_launch(void* const* d_in, const int* in_sizes, int n_in,
                              void* d_out, int out_size) {
    const float* sem    = (const float*)d_in[0];
    const float* center = (const float*)d_in[1];
    const float* sizes  = (const float*)d_in[2];
    const float* gious  = (const float*)d_in[3];
    const int*   labels = (const int*)d_in[4];
    const int*   na     = (const int*)d_in[5];

    float* out      = (float*)d_out;
    float* out_inds = out;
    float* out_mask = out + (size_t)BB * QQ;
    float* fc       = out + (size_t)2 * BB * QQ;   // final_cost region

    prep_kernel<<<1, 512>>>(labels, na);
    cost_transpose_kernel<<<dim3(QQ/32, GG/32, BB), dim3(32, 8)>>>(sem, center, sizes, gious, fc);
    lsa_kernel<<<BB, NT>>>(out_inds, out_mask);
}

// round 10
// speedup vs baseline: 1.3996x; 1.0588x over previous
#include <cuda_runtime.h>
#include <math.h>
#include <cfloat>

#define BB 8
#define QQ 2048
#define GG 128
#define CC 512
#define NT 128
#define NW (NT/32)           // 4 warps
#define NCH 4                // column chunks (512 cols each)
#define CHW 512              // chunk width
#define CP 16                // columns per thread (4 chunks x 4 contiguous)
#define MAXPATH 140          // path entries: dummy + <=G matched + slack

typedef unsigned long long u64;

// ---------------- device scratch (no allocation allowed) ----------------
__device__ float g_ct[BB*GG*QQ];   // transposed cost: CT[b][g][q]  (8 MB)
__device__ int   g_labels[BB*GG];
__device__ int   g_na[BB];

// ---------------- prep: normalize int inputs (int32 vs int64 on disk) ----
__global__ void prep_kernel(const int* __restrict__ lab_raw,
                            const int* __restrict__ na_raw) {
    __shared__ int nzl, nzn;
    int t = threadIdx.x;
    if (t == 0) { nzl = 0; nzn = 0; }
    __syncthreads();
    for (int k = t; k < (BB*GG)/2; k += blockDim.x)
        if (lab_raw[2*k+1] != 0) atomicExch(&nzl, 1);
    for (int k = t; k < BB/2; k += blockDim.x)
        if (na_raw[2*k+1] != 0) atomicExch(&nzn, 1);
    __syncthreads();
    bool l64 = (nzl == 0), n64 = (nzn == 0);
    for (int k = t; k < BB*GG; k += blockDim.x)
        g_labels[k] = l64 ? lab_raw[2*k] : lab_raw[k];
    if (t < BB)
        g_na[t] = n64 ? na_raw[2*t] : na_raw[t];
}

// ------- fused cost + transpose: fc[b][q][g] and CT[b][g][q] in one pass -----
__global__ void cost_transpose_kernel(const float* __restrict__ sem,
                                      const float* __restrict__ center,
                                      const float* __restrict__ sizes,
                                      const float* __restrict__ gious,
                                      float* __restrict__ fc) {
    __shared__ float tile[32][33];
    int b = blockIdx.z;
    int q0 = blockIdx.x * 32, g0 = blockIdx.y * 32;
    int x = threadIdx.x;
    int g = g0 + x;
    int lab = g_labels[b*GG + g];
    for (int r = threadIdx.y; r < 32; r += 8) {
        int q = q0 + r;
        float s = sem[((size_t)(b*QQ + q))*CC + lab];
        // XLA lowers lax.logistic as 0.5 + 0.5*tanh(0.5*x)
        float p = 0.5f + 0.5f * tanhf(0.5f * s);
        float pos = 0.25f * (1.0f - p) * (1.0f - p) * (-logf(p + 1e-8f));
        float neg = 0.75f * p * p * (-log1pf(-(p - 1e-8f)));
        float diff = pos - neg;
        size_t idx = ((size_t)(b*QQ + q))*GG + g;
        float val = 2.0f*diff + 5.0f*center[idx] + 1.0f*sizes[idx] - 2.0f*gious[idx];
        fc[idx] = val;                 // coalesced along g
        tile[r][x] = val;
    }
    __syncthreads();
    for (int r = threadIdx.y; r < 32; r += 8)
        g_ct[((size_t)(b*GG + g0 + r))*QQ + q0 + x] = tile[x][r];  // coalesced along q
}

// --------- order-preserving keys (monotone) -----------------------------
__device__ __forceinline__ unsigned fkey(float f) {
    unsigned u = __float_as_uint(f);
    return (u & 0x80000000u) ? ~u : (u | 0x80000000u);
}
__device__ __forceinline__ float finv(unsigned k) {
    unsigned u = (k & 0x80000000u) ? (k & 0x7fffffffu) : ~k;
    return __uint_as_float(u);
}
__device__ __forceinline__ u64 dkey(double d) {
    u64 b = (u64)__double_as_longlong(d);
    return (b & 0x8000000000000000ull) ? ~b : (b | 0x8000000000000000ull);
}

// ---------------- LSA: exact replica of the reference's algorithm -------
// 4 warps, 16 cols/thread (4 contiguous float4 chunks), rows + v-shadow
// register-resident, per-warp REDUX mins, 2 barriers/iteration, winner via
// a single shared atomicMin-u64 (quantized fp64 key | col; exact delta from
// a side array), speculative next-row prefetch directly into r[], lazy-delta
// bit-exact write-back.
__global__ void __launch_bounds__(NT, 1) lsa_kernel(float* __restrict__ out_inds,
                                                    float* __restrict__ out_mask) {
    __shared__ double v[QQ];            // fp64 master potentials (0-based cols)
    __shared__ __align__(16) float vf[QQ];  // fp32 shadow master
    __shared__ double u[GG + 1];        // rows 1..GG
    __shared__ short  p[QQ];            // matched row per col (0 = free)
    __shared__ unsigned short ulist[MAXPATH];
    __shared__ double sdelta[MAXPATH];
    __shared__ __align__(16) unsigned swm[NW];   // per-warp exact fp32 min key
    __shared__ __align__(16) unsigned swp[NW];   // per-warp (key21|col11) min
    __shared__ double cval[QQ];         // exact fp64 reduced cost of posted cols
    __shared__ u64 slot[2];             // ping-pong winner keys

    int b = blockIdx.x;
    int tid = threadIdx.x;
    int lane = tid & 31, wid = tid >> 5;
    const float* CT = g_ct + (size_t)b * GG * QQ;
    const int cbase = tid << 2;         // my 4 cols within each chunk start here

    int na = g_na[b];
    if (na < 0) na = 0;
    if (na > GG) na = GG;

    for (int jj = tid; jj < QQ; jj += NT) { v[jj] = 0.0; vf[jj] = 0.0f; p[jj] = 0; }
    for (int jj = tid; jj <= GG; jj += NT) u[jj] = 0.0;
    if (tid == 0) { ulist[0] = 0; slot[0] = ~0ull; slot[1] = ~0ull; }
    __syncthreads();

    float r[CP], w[CP], c[CP];
    #pragma unroll
    for (int k = 0; k < CP; k++) { r[k] = 0.f; w[k] = 0.f; }
    int pre_i0 = -1;
    int it = 0;                         // global iteration parity counter

    if (na > 0) {                        // warm prefetch: row 1
        #pragma unroll
        for (int ch = 0; ch < NCH; ch++) {
            float4 t = *(const float4*)(CT + ch*CHW + cbase);
            r[ch*4+0] = t.x; r[ch*4+1] = t.y; r[ch*4+2] = t.z; r[ch*4+3] = t.w;
        }
        pre_i0 = 1;
    }

    for (int i = 1; i <= na; i++) {
        int cnt = 1;                    // path length incl. dummy (redundant)
        int i0 = i;
        double ui = u[i];
        float uif = (float)ui;
        int fbj = 0;

        for (;;) {
            if (pre_i0 != i0) {         // mispredict: synchronous reload (uniform)
                const float* row = CT + (size_t)(i0 - 1) * QQ;
                #pragma unroll
                for (int ch = 0; ch < NCH; ch++) {
                    float4 t = *(const float4*)(row + ch*CHW + cbase);
                    r[ch*4+0] = t.x; r[ch*4+1] = t.y; r[ch*4+2] = t.z; r[ch*4+3] = t.w;
                }
                pre_i0 = i0;
            }

            // ---- phase 1: register scan + balanced min / argmin trees ----
            #pragma unroll
            for (int k = 0; k < CP; k++) c[k] = (r[k] - uif) - w[k];
            float t8[8];
            #pragma unroll
            for (int k = 0; k < 8; k++) t8[k] = fminf(c[2*k], c[2*k+1]);
            float t4a = fminf(t8[0], t8[1]), t4b = fminf(t8[2], t8[3]);
            float t4c = fminf(t8[4], t8[5]), t4d = fminf(t8[6], t8[7]);
            float m = fminf(fminf(t4a, t4b), fminf(t4c, t4d));
            int e[CP];
            #pragma unroll
            for (int k = 0; k < CP; k++) {
                int col = (k >> 2)*CHW + cbase + (k & 3);
                e[k] = (c[k] == m) ? col : 0x7FF;
            }
            int s8[8];
            #pragma unroll
            for (int k = 0; k < 8; k++) s8[k] = min(e[2*k], e[2*k+1]);
            int s4a = min(s8[0], s8[1]), s4b = min(s8[2], s8[3]);
            int s4c = min(s8[4], s8[5]), s4d = min(s8[6], s8[7]);
            int mj = min(min(s4a, s4b), min(s4c, s4d));

            unsigned km = fkey(m);
            unsigned kp = (km & 0xFFFFF800u) | (unsigned)mj;  // 21b key | 11b col
            unsigned wkm = __reduce_min_sync(0xffffffffu, km);
            unsigned wkp = __reduce_min_sync(0xffffffffu, kp);
            if (lane == 0) { swm[wid] = wkm; swp[wid] = wkp; }
            __syncthreads();            // B1

            // ---- phase 2: fold, post candidates, speculative load into r[] ----
            uint4 ma = *(const uint4*)&swm[0];
            uint4 pa = *(const uint4*)&swp[0];
            unsigned gm_ = umin(umin(ma.x, ma.y), umin(ma.z, ma.w));
            unsigned gp_ = umin(umin(pa.x, pa.y), umin(pa.z, pa.w));

            int gj = (int)(gp_ & 0x7FFu);             // approx fp32 argmin col
            int pg = p[gj];
            int spec = (pg == 0) ? ((i < na) ? (i + 1) : i0) : pg;

            float thr = finv(gm_) + 1e-3f;            // exact fp32 min + margin
            if (m <= thr) {
                #pragma unroll
                for (int k = 0; k < CP; k++) {
                    if (c[k] <= thr) {
                        int col = (k >> 2)*CHW + cbase + (k & 3);
                        double cd = ((double)r[k] - ui) - v[col];
                        cval[col] = cd;               // exact value, race-free (distinct cols)
                        atomicMin(&slot[it & 1], (dkey(cd) & ~0x7FFull) | (u64)col);
                    }
                }
            }
            if (tid == 0) slot[(it + 1) & 1] = ~0ull; // reset other slot for next iter

            {                                          // speculative load directly into r[]
                const float* rs = CT + (size_t)(spec - 1) * QQ;
                #pragma unroll
                for (int ch = 0; ch < NCH; ch++) {
                    float4 t = *(const float4*)(rs + ch*CHW + cbase);
                    r[ch*4+0] = t.x; r[ch*4+1] = t.y; r[ch*4+2] = t.z; r[ch*4+3] = t.w;
                }
                pre_i0 = spec;
            }
            __syncthreads();            // B2

            // ---- phase 3: decode winner (3 LDS), update redundant state ----
            u64 win = slot[it & 1];
            it++;
            int bj = (int)(win & 0x7FFull);
            double delta = cval[bj];                   // exact fp64 of chosen col
            if (tid == 0) sdelta[cnt - 1] = delta;     // delta of step cnt-1
            int pb = p[bj];

            if (pb == 0) {
                fbj = bj;               // way==0 => single-step backtrack
                break;                  // r[] already holds the speculated next row
            }
            if (tid == 0) ulist[cnt] = (unsigned short)bj;  // joins at step cnt
            cnt++;
            i0 = pb;
            ui = u[pb];
            uif = (float)ui;
            {                            // mark used locally if one of my cols
                int o = bj - cbase;
                #pragma unroll
                for (int k = 0; k < CP; k++)
                    if (o == (k >> 2)*CHW + (k & 3)) w[k] = -FLT_MAX;
            }
        }

        __syncthreads();                // S1: ulist/sdelta writes visible

        // ---- parallel bit-exact write-back: entry k gets deltas k..cnt-1 ----
        if (tid < cnt) {
            if (tid == 0) {              // dummy column: u[i] only (v[dummy] never read)
                double uu = u[i];
                for (int t = 0; t < cnt; t++) uu += sdelta[t];
                u[i] = uu;
            } else {
                int col = ulist[tid];
                int ik = p[col];
                double uu = u[ik];
                double vv = v[col];
                for (int t = tid; t < cnt; t++) {     // ascending t == reference order
                    double d = sdelta[t];
                    uu += d;
                    vv -= d;
                }
                u[ik] = uu;
                v[col] = vv;
                vf[col] = (float)vv;     // restore shadow master
            }
        }
        if (tid == 0) p[fbj] = (short)i;              // assign final unmatched column
        __syncthreads();                // S2: write-back visible

        // refresh register shadow (clears sentinels, picks up new v values)
        #pragma unroll
        for (int ch = 0; ch < NCH; ch++) {
            float4 t = *(const float4*)(vf + ch*CHW + cbase);
            w[ch*4+0] = t.x; w[ch*4+1] = t.y; w[ch*4+2] = t.z; w[ch*4+3] = t.w;
        }
    }

    // outputs: proposal col matched to gt p[col]-1
    for (int jj = tid; jj < QQ; jj += NT) {
        int pj = p[jj];
        size_t o = (size_t)b * QQ + jj;
        out_inds[o] = (pj > 0) ? (float)(pj - 1) : 0.0f;
        out_mask[o] = (pj > 0) ? 1.0f : 0.0f;
    }
}

// ---------------- launch ------------------------------------------------
extern "C" void kernel_launch(void* const* d_in, const int* in_sizes, int n_in,
                              void* d_out, int out_size) {
    const float* sem    = (const float*)d_in[0];
    const float* center = (const float*)d_in[1];
    const float* sizes  = (const float*)d_in[2];
    const float* gious  = (const float*)d_in[3];
    const int*   labels = (const int*)d_in[4];
    const int*   na     = (const int*)d_in[5];

    float* out      = (float*)d_out;
    float* out_inds = out;
    float* out_mask = out + (size_t)BB * QQ;
    float* fc       = out + (size_t)2 * BB * QQ;   // final_cost region

    prep_kernel<<<1, 512>>>(labels, na);
    cost_transpose_kernel<<<dim3(QQ/32, GG/32, BB), dim3(32, 8)>>>(sem, center, sizes, gious, fc);
    lsa_kernel<<<BB, NT>>>(out_inds, out_mask);
}